// round 1
// baseline (speedup 1.0000x reference)
#include <cuda_runtime.h>
#include <cuda_bf16.h>
#include <cstdint>

// ---------------- Problem-size constants (fixed instance) ----------------
#define N_ATOMS_MAX  100000
#define N_BONDS_MAX  200000
#define H_DIM        300
#define H4_DIM       75        // H/4

// ---------------- Device scratch (static, allocation-free) ----------------
__device__ float g_inp  [(size_t)N_BONDS_MAX * H_DIM];   // f_bonds @ W_i
__device__ float g_msgA [(size_t)N_BONDS_MAX * H_DIM];
__device__ float g_msgB [(size_t)N_BONDS_MAX * H_DIM];
__device__ float g_bdiff[(size_t)N_BONDS_MAX * H_DIM];
__device__ float g_amsg [(size_t)N_ATOMS_MAX * H_DIM];
__device__ float g_ahid [(size_t)N_ATOMS_MAX * H_DIM];

// ---------------- SGEMM config ----------------
#define BM 64
#define BN 64
#define BK 8
// 256 threads, each computes a 4x4 micro-tile.

// Shared-tile loaders common to all GEMM variants.
// As stored transposed: As[k][m], Bs[k][n].

// epilogue modes are baked into separate kernels for simplicity.

// ---- GEMM 1: inp = A @ B ; also msg = relu(inp). A:[M,K] row-major, B:[K,N] ----
__global__ void gemm_in_kernel(const float* __restrict__ A, const float* __restrict__ B,
                               float* __restrict__ out_inp, float* __restrict__ out_msg,
                               int M, int K, int N)
{
    __shared__ float As[BK][BM];
    __shared__ float Bs[BK][BN];
    const int tid = threadIdx.x;
    const int tx = tid & 15, ty = tid >> 4;
    const int rowBase = blockIdx.y * BM;
    const int colBase = blockIdx.x * BN;

    float acc[4][4] = {};

    for (int kk = 0; kk < K; kk += BK) {
        #pragma unroll
        for (int l = 0; l < 2; ++l) {
            int e = tid * 2 + l;          // 0..511
            int r = e >> 3, c = e & 7;    // r: row in tile, c: k
            int gr = rowBase + r, gc = kk + c;
            As[c][r] = (gr < M && gc < K) ? A[(size_t)gr * K + gc] : 0.f;
        }
        #pragma unroll
        for (int l = 0; l < 2; ++l) {
            int e = tid * 2 + l;
            int r = e >> 6, c = e & 63;
            int gr = kk + r, gc = colBase + c;
            Bs[r][c] = (gr < K && gc < N) ? B[(size_t)gr * N + gc] : 0.f;
        }
        __syncthreads();
        #pragma unroll
        for (int k = 0; k < BK; ++k) {
            float a[4], b[4];
            #pragma unroll
            for (int i = 0; i < 4; ++i) a[i] = As[k][ty * 4 + i];
            #pragma unroll
            for (int j = 0; j < 4; ++j) b[j] = Bs[k][tx * 4 + j];
            #pragma unroll
            for (int i = 0; i < 4; ++i)
                #pragma unroll
                for (int j = 0; j < 4; ++j)
                    acc[i][j] = fmaf(a[i], b[j], acc[i][j]);
        }
        __syncthreads();
    }

    #pragma unroll
    for (int i = 0; i < 4; ++i) {
        int gr = rowBase + ty * 4 + i;
        if (gr >= M) continue;
        #pragma unroll
        for (int j = 0; j < 4; ++j) {
            int gc = colBase + tx * 4 + j;
            if (gc >= N) continue;
            float v = acc[i][j];
            out_inp[(size_t)gr * N + gc] = v;
            out_msg[(size_t)gr * N + gc] = fmaxf(v, 0.f);
        }
    }
}

// ---- GEMM 2: msg_out = relu(inp + A @ B) ----
__global__ void gemm_h_kernel(const float* __restrict__ A, const float* __restrict__ B,
                              const float* __restrict__ inp, float* __restrict__ out_msg,
                              int M, int K, int N)
{
    __shared__ float As[BK][BM];
    __shared__ float Bs[BK][BN];
    const int tid = threadIdx.x;
    const int tx = tid & 15, ty = tid >> 4;
    const int rowBase = blockIdx.y * BM;
    const int colBase = blockIdx.x * BN;

    float acc[4][4] = {};

    for (int kk = 0; kk < K; kk += BK) {
        #pragma unroll
        for (int l = 0; l < 2; ++l) {
            int e = tid * 2 + l;
            int r = e >> 3, c = e & 7;
            int gr = rowBase + r, gc = kk + c;
            As[c][r] = (gr < M && gc < K) ? A[(size_t)gr * K + gc] : 0.f;
        }
        #pragma unroll
        for (int l = 0; l < 2; ++l) {
            int e = tid * 2 + l;
            int r = e >> 6, c = e & 63;
            int gr = kk + r, gc = colBase + c;
            Bs[r][c] = (gr < K && gc < N) ? B[(size_t)gr * N + gc] : 0.f;
        }
        __syncthreads();
        #pragma unroll
        for (int k = 0; k < BK; ++k) {
            float a[4], b[4];
            #pragma unroll
            for (int i = 0; i < 4; ++i) a[i] = As[k][ty * 4 + i];
            #pragma unroll
            for (int j = 0; j < 4; ++j) b[j] = Bs[k][tx * 4 + j];
            #pragma unroll
            for (int i = 0; i < 4; ++i)
                #pragma unroll
                for (int j = 0; j < 4; ++j)
                    acc[i][j] = fmaf(a[i], b[j], acc[i][j]);
        }
        __syncthreads();
    }

    #pragma unroll
    for (int i = 0; i < 4; ++i) {
        int gr = rowBase + ty * 4 + i;
        if (gr >= M) continue;
        #pragma unroll
        for (int j = 0; j < 4; ++j) {
            int gc = colBase + tx * 4 + j;
            if (gc >= N) continue;
            size_t idx = (size_t)gr * N + gc;
            out_msg[idx] = fmaxf(inp[idx] + acc[i][j], 0.f);
        }
    }
}

// ---- GEMM 3 (readout): ahid = relu([f_atoms | amsg] @ W_o + b_o) ----
// A(i,k) = k < AF ? f_atoms[i*AF+k] : amsg[i*H + (k-AF)], K = AF + H.
__global__ void gemm_o_kernel(const float* __restrict__ f_atoms, const float* __restrict__ amsg,
                              const float* __restrict__ B, const float* __restrict__ bias,
                              float* __restrict__ out,
                              int M, int AF, int Hh, int N)
{
    __shared__ float As[BK][BM];
    __shared__ float Bs[BK][BN];
    const int tid = threadIdx.x;
    const int tx = tid & 15, ty = tid >> 4;
    const int rowBase = blockIdx.y * BM;
    const int colBase = blockIdx.x * BN;
    const int K = AF + Hh;

    float acc[4][4] = {};

    for (int kk = 0; kk < K; kk += BK) {
        #pragma unroll
        for (int l = 0; l < 2; ++l) {
            int e = tid * 2 + l;
            int r = e >> 3, c = e & 7;
            int gr = rowBase + r, gc = kk + c;
            float v = 0.f;
            if (gr < M && gc < K) {
                v = (gc < AF) ? f_atoms[(size_t)gr * AF + gc]
                              : amsg[(size_t)gr * Hh + (gc - AF)];
            }
            As[c][r] = v;
        }
        #pragma unroll
        for (int l = 0; l < 2; ++l) {
            int e = tid * 2 + l;
            int r = e >> 6, c = e & 63;
            int gr = kk + r, gc = colBase + c;
            Bs[r][c] = (gr < K && gc < N) ? B[(size_t)gr * N + gc] : 0.f;
        }
        __syncthreads();
        #pragma unroll
        for (int k = 0; k < BK; ++k) {
            float a[4], b[4];
            #pragma unroll
            for (int i = 0; i < 4; ++i) a[i] = As[k][ty * 4 + i];
            #pragma unroll
            for (int j = 0; j < 4; ++j) b[j] = Bs[k][tx * 4 + j];
            #pragma unroll
            for (int i = 0; i < 4; ++i)
                #pragma unroll
                for (int j = 0; j < 4; ++j)
                    acc[i][j] = fmaf(a[i], b[j], acc[i][j]);
        }
        __syncthreads();
    }

    #pragma unroll
    for (int i = 0; i < 4; ++i) {
        int gr = rowBase + ty * 4 + i;
        if (gr >= M) continue;
        #pragma unroll
        for (int j = 0; j < 4; ++j) {
            int gc = colBase + tx * 4 + j;
            if (gc >= N) continue;
            out[(size_t)gr * N + gc] = fmaxf(acc[i][j] + bias[gc], 0.f);
        }
    }
}

// ---- Gather: amsg[a] = sum_nb msg[a2b[a][nb]]  (float4 over H) ----
__global__ void gather_atoms_kernel(const float* __restrict__ msg, const int* __restrict__ a2b,
                                    float* __restrict__ amsg, int n_atoms, int max_nb)
{
    int idx = blockIdx.x * blockDim.x + threadIdx.x;
    int total = n_atoms * H4_DIM;
    if (idx >= total) return;
    int atom = idx / H4_DIM;
    int h4   = idx - atom * H4_DIM;
    float4 s = make_float4(0.f, 0.f, 0.f, 0.f);
    for (int nb = 0; nb < max_nb; ++nb) {
        int b = __ldg(&a2b[(size_t)atom * max_nb + nb]);
        float4 v = *((const float4*)(msg + (size_t)b * H_DIM) + h4);
        s.x += v.x; s.y += v.y; s.z += v.z; s.w += v.w;
    }
    ((float4*)amsg)[idx] = s;
}

// ---- Bond diff: bdiff[b] = amsg[b2a[b]] - msg[b2revb[b]] ----
__global__ void bond_diff_kernel(const float* __restrict__ amsg, const float* __restrict__ msg,
                                 const int* __restrict__ b2a, const int* __restrict__ b2revb,
                                 float* __restrict__ bdiff, int n_bonds)
{
    int idx = blockIdx.x * blockDim.x + threadIdx.x;
    int total = n_bonds * H4_DIM;
    if (idx >= total) return;
    int b  = idx / H4_DIM;
    int h4 = idx - b * H4_DIM;
    int sa = __ldg(&b2a[b]);
    int rb = __ldg(&b2revb[b]);
    float4 am = *((const float4*)(amsg + (size_t)sa * H_DIM) + h4);
    float4 mv = *((const float4*)(msg  + (size_t)rb * H_DIM) + h4);
    float4 r = make_float4(am.x - mv.x, am.y - mv.y, am.z - mv.z, am.w - mv.w);
    ((float4*)bdiff)[idx] = r;
}

// ---- Segment mean: out[m] = mean over atoms with atom_mol==m of ahid (sorted mol ids) ----
__global__ void segmean_kernel(const float* __restrict__ ahid, const int* __restrict__ atom_mol,
                               float* __restrict__ out, int n_atoms, int Hh)
{
    const int m = blockIdx.x;
    __shared__ int s_bounds[2];
    if (threadIdx.x == 0) {
        int lo = 0, hi = n_atoms;
        while (lo < hi) { int mid = (lo + hi) >> 1; if (atom_mol[mid] < m) lo = mid + 1; else hi = mid; }
        s_bounds[0] = lo;
        hi = n_atoms;
        while (lo < hi) { int mid = (lo + hi) >> 1; if (atom_mol[mid] < m + 1) lo = mid + 1; else hi = mid; }
        s_bounds[1] = lo;
    }
    __syncthreads();
    const int start = s_bounds[0], end = s_bounds[1];
    const float inv = (end > start) ? 1.f / (float)(end - start) : 0.f;
    for (int h = threadIdx.x; h < Hh; h += blockDim.x) {
        float s = 0.f;
        for (int a = start; a < end; ++a) s += ahid[(size_t)a * Hh + h];
        out[(size_t)m * Hh + h] = s * inv;
    }
}

// ---------------- Launch ----------------
extern "C" void kernel_launch(void* const* d_in, const int* in_sizes, int n_in,
                              void* d_out, int out_size)
{
    const float* f_atoms = (const float*)d_in[0];
    const float* f_bonds = (const float*)d_in[1];
    const float* W_i     = (const float*)d_in[2];
    const float* W_h     = (const float*)d_in[3];
    const float* W_o     = (const float*)d_in[4];
    const float* b_o     = (const float*)d_in[5];
    const int*   a2b     = (const int*)d_in[6];
    const int*   b2a     = (const int*)d_in[7];
    const int*   b2revb  = (const int*)d_in[8];
    const int*   atom_mol= (const int*)d_in[9];

    const int H       = in_sizes[5];             // 300
    const int n_bonds = in_sizes[7];             // 200000
    const int n_atoms = in_sizes[9];             // 100000
    const int BF      = in_sizes[1] / n_bonds;   // 147
    const int AF      = in_sizes[0] / n_atoms;   // 133
    const int max_nb  = in_sizes[6] / n_atoms;   // 6
    const int n_mols  = out_size / H;            // 4000

    float* inp   = nullptr; cudaGetSymbolAddress((void**)&inp,   g_inp);
    float* msgA  = nullptr; cudaGetSymbolAddress((void**)&msgA,  g_msgA);
    float* msgB  = nullptr; cudaGetSymbolAddress((void**)&msgB,  g_msgB);
    float* bdiff = nullptr; cudaGetSymbolAddress((void**)&bdiff, g_bdiff);
    float* amsg  = nullptr; cudaGetSymbolAddress((void**)&amsg,  g_amsg);
    float* ahid  = nullptr; cudaGetSymbolAddress((void**)&ahid,  g_ahid);

    dim3 blk(256);
    dim3 grid_b((H + BN - 1) / BN, (n_bonds + BM - 1) / BM);   // GEMMs over bonds
    dim3 grid_a((H + BN - 1) / BN, (n_atoms + BM - 1) / BM);   // readout GEMM over atoms

    const int thr = 256;
    int gatherBlocks = (n_atoms * H4_DIM + thr - 1) / thr;
    int diffBlocks   = (n_bonds * H4_DIM + thr - 1) / thr;

    // 1) inp = f_bonds @ W_i ; msgA = relu(inp)
    gemm_in_kernel<<<grid_b, blk>>>(f_bonds, W_i, inp, msgA, n_bonds, BF, H);

    // 2) depth iteration 1: msgB = relu(inp + (gather-diff(msgA)) @ W_h)
    gather_atoms_kernel<<<gatherBlocks, thr>>>(msgA, a2b, amsg, n_atoms, max_nb);
    bond_diff_kernel<<<diffBlocks, thr>>>(amsg, msgA, b2a, b2revb, bdiff, n_bonds);
    gemm_h_kernel<<<grid_b, blk>>>(bdiff, W_h, inp, msgB, n_bonds, H, H);

    // 3) depth iteration 2: msgA = relu(inp + (gather-diff(msgB)) @ W_h)
    gather_atoms_kernel<<<gatherBlocks, thr>>>(msgB, a2b, amsg, n_atoms, max_nb);
    bond_diff_kernel<<<diffBlocks, thr>>>(amsg, msgB, b2a, b2revb, bdiff, n_bonds);
    gemm_h_kernel<<<grid_b, blk>>>(bdiff, W_h, inp, msgA, n_bonds, H, H);

    // 4) final atom aggregation
    gather_atoms_kernel<<<gatherBlocks, thr>>>(msgA, a2b, amsg, n_atoms, max_nb);

    // 5) readout: ahid = relu([f_atoms | amsg] @ W_o + b_o)
    gemm_o_kernel<<<grid_a, blk>>>(f_atoms, amsg, W_o, b_o, ahid, n_atoms, AF, H, H);

    // 6) per-molecule mean
    segmean_kernel<<<n_mols, 256>>>(ahid, atom_mol, (float*)d_out, n_atoms, H);
}

// round 2
// speedup vs baseline: 1.1617x; 1.1617x over previous
#include <cuda_runtime.h>
#include <cstdint>

// ---------------- Problem-size constants (fixed instance) ----------------
#define N_ATOMS_MAX  100000
#define N_BONDS_MAX  200000
#define H_DIM        300
#define H4_DIM       75

// ---------------- Device scratch (static, allocation-free) ----------------
__device__ float g_inp [(size_t)N_BONDS_MAX * H_DIM];
__device__ float g_msgA[(size_t)N_BONDS_MAX * H_DIM];
__device__ float g_msgB[(size_t)N_BONDS_MAX * H_DIM];
__device__ float g_amsg[(size_t)N_ATOMS_MAX * H_DIM];
__device__ float g_ahid[(size_t)N_ATOMS_MAX * H_DIM];

// ---------------- TF32 tensor-core GEMM config ----------------
#define BM 128
#define BN 128
#define BK 16
#define SK 20   // padded smem row stride (floats) -> conflict-free fragment loads

__device__ __forceinline__ uint32_t f2tf(float f) {
    uint32_t u;
    asm("cvt.rna.tf32.f32 %0, %1;" : "=r"(u) : "f"(f));
    return u;
}

__device__ __forceinline__ void mma8(float* c, const uint32_t* a, const uint32_t* b) {
    asm volatile(
        "mma.sync.aligned.m16n8k8.row.col.f32.tf32.tf32.f32 "
        "{%0,%1,%2,%3}, {%4,%5,%6,%7}, {%8,%9}, {%0,%1,%2,%3};\n"
        : "+f"(c[0]), "+f"(c[1]), "+f"(c[2]), "+f"(c[3])
        : "r"(a[0]), "r"(a[1]), "r"(a[2]), "r"(a[3]), "r"(b[0]), "r"(b[1]));
}

// Warp layout: 8 warps; wm = wid>>2 (2 warps over M, 64 rows each),
// wn = wid&3 (4 warps over N, 32 cols each). Per-warp tile 64x32 = 4x4 mma atoms.
__device__ __forceinline__ void compute_tile(const uint32_t (*As)[SK], const uint32_t (*Bs)[SK],
                                             float acc[4][4][4], int wm, int wn, int g, int tg)
{
    #pragma unroll
    for (int ks = 0; ks < BK; ks += 8) {
        uint32_t af[4][4], bf[4][2];
        #pragma unroll
        for (int mi = 0; mi < 4; ++mi) {
            int r = wm * 64 + mi * 16 + g;
            af[mi][0] = As[r][ks + tg];
            af[mi][1] = As[r + 8][ks + tg];
            af[mi][2] = As[r][ks + tg + 4];
            af[mi][3] = As[r + 8][ks + tg + 4];
        }
        #pragma unroll
        for (int ni = 0; ni < 4; ++ni) {
            int c = wn * 32 + ni * 8 + g;
            bf[ni][0] = Bs[c][ks + tg];
            bf[ni][1] = Bs[c][ks + tg + 4];
        }
        #pragma unroll
        for (int mi = 0; mi < 4; ++mi)
            #pragma unroll
            for (int ni = 0; ni < 4; ++ni)
                mma8(acc[mi][ni], af[mi], bf[ni]);
    }
}

// Stage B tile [BK x BN] (weights, row-major [K,N]) into Bs[n][k], tf32-converted.
__device__ __forceinline__ void stage_B(uint32_t (*Bs)[SK], const float* __restrict__ Bg,
                                        int kk, int colBase, int K, int N, int tid)
{
    int bk = tid >> 4;            // 0..15
    int nb = (tid & 15) * 8;      // 0..120
    int gk = kk + bk;
    bool kok = gk < K;
    const float* src = Bg + (size_t)(kok ? gk : 0) * N;
    #pragma unroll
    for (int j = 0; j < 8; ++j) {
        int gc = colBase + nb + j;
        float v = (kok && gc < N) ? src[gc] : 0.f;
        Bs[nb + j][bk] = f2tf(v);
    }
}

// ---- GEMM 1: inp = f_bonds @ W_i ; msg = relu(inp) ----
__global__ __launch_bounds__(256)
void gemm_in_tc(const float* __restrict__ A, const float* __restrict__ B,
                float* __restrict__ out_inp, float* __restrict__ out_msg,
                int M, int K, int N)
{
    __shared__ uint32_t As[BM][SK];
    __shared__ uint32_t Bs[BN][SK];
    const int tid = threadIdx.x;
    const int lane = tid & 31, wid = tid >> 5;
    const int wm = wid >> 2, wn = wid & 3;
    const int g = lane >> 2, tg = lane & 3;
    const int rowBase = blockIdx.y * BM, colBase = blockIdx.x * BN;

    float acc[4][4][4] = {};

    const int arow = tid >> 1;
    const int acb = (tid & 1) * 8;
    const int gr0 = rowBase + arow;
    const bool rok = gr0 < M;
    const float* asrc = A + (size_t)(rok ? gr0 : (M - 1)) * K;

    for (int kk = 0; kk < K; kk += BK) {
        #pragma unroll
        for (int j = 0; j < 8; ++j) {
            int gk = kk + acb + j;
            float v = (rok && gk < K) ? asrc[gk] : 0.f;
            As[arow][acb + j] = f2tf(v);
        }
        stage_B(Bs, B, kk, colBase, K, N, tid);
        __syncthreads();
        compute_tile(As, Bs, acc, wm, wn, g, tg);
        __syncthreads();
    }

    #pragma unroll
    for (int mi = 0; mi < 4; ++mi) {
        int r0 = rowBase + wm * 64 + mi * 16 + g;
        #pragma unroll
        for (int ni = 0; ni < 4; ++ni) {
            int c0 = colBase + wn * 32 + ni * 8 + 2 * tg;
            if (c0 >= N) continue;
            if (r0 < M) {
                size_t o = (size_t)r0 * N + c0;
                out_inp[o]     = acc[mi][ni][0];
                out_inp[o + 1] = acc[mi][ni][1];
                out_msg[o]     = fmaxf(acc[mi][ni][0], 0.f);
                out_msg[o + 1] = fmaxf(acc[mi][ni][1], 0.f);
            }
            if (r0 + 8 < M) {
                size_t o = (size_t)(r0 + 8) * N + c0;
                out_inp[o]     = acc[mi][ni][2];
                out_inp[o + 1] = acc[mi][ni][3];
                out_msg[o]     = fmaxf(acc[mi][ni][2], 0.f);
                out_msg[o + 1] = fmaxf(acc[mi][ni][3], 0.f);
            }
        }
    }
}

// ---- GEMM 2 (fused diff): out = relu(inp + (amsg[b2a] - msg[b2revb]) @ W_h) ----
__global__ __launch_bounds__(256)
void gemm_h_tc(const float* __restrict__ amsg, const float* __restrict__ msg,
               const int* __restrict__ b2a, const int* __restrict__ b2revb,
               const float* __restrict__ B, const float* __restrict__ inp,
               float* __restrict__ out_msg, int M, int K, int N)
{
    __shared__ uint32_t As[BM][SK];
    __shared__ uint32_t Bs[BN][SK];
    __shared__ const float* s_pa[BM];
    __shared__ const float* s_pm[BM];
    const int tid = threadIdx.x;
    const int lane = tid & 31, wid = tid >> 5;
    const int wm = wid >> 2, wn = wid & 3;
    const int g = lane >> 2, tg = lane & 3;
    const int rowBase = blockIdx.y * BM, colBase = blockIdx.x * BN;

    if (tid < BM) {
        int gr = rowBase + tid;
        if (gr >= M) gr = M - 1;
        s_pa[tid] = amsg + (size_t)b2a[gr] * K;
        s_pm[tid] = msg + (size_t)b2revb[gr] * K;
    }
    __syncthreads();

    float acc[4][4][4] = {};

    const int arow = tid >> 1;
    const int acb = (tid & 1) * 8;
    const float* pa = s_pa[arow];
    const float* pm = s_pm[arow];

    for (int kk = 0; kk < K; kk += BK) {
        #pragma unroll
        for (int j = 0; j < 8; ++j) {
            int gk = kk + acb + j;
            float v = (gk < K) ? (pa[gk] - pm[gk]) : 0.f;
            As[arow][acb + j] = f2tf(v);
        }
        stage_B(Bs, B, kk, colBase, K, N, tid);
        __syncthreads();
        compute_tile(As, Bs, acc, wm, wn, g, tg);
        __syncthreads();
    }

    #pragma unroll
    for (int mi = 0; mi < 4; ++mi) {
        int r0 = rowBase + wm * 64 + mi * 16 + g;
        #pragma unroll
        for (int ni = 0; ni < 4; ++ni) {
            int c0 = colBase + wn * 32 + ni * 8 + 2 * tg;
            if (c0 >= N) continue;
            if (r0 < M) {
                size_t o = (size_t)r0 * N + c0;
                out_msg[o]     = fmaxf(inp[o]     + acc[mi][ni][0], 0.f);
                out_msg[o + 1] = fmaxf(inp[o + 1] + acc[mi][ni][1], 0.f);
            }
            if (r0 + 8 < M) {
                size_t o = (size_t)(r0 + 8) * N + c0;
                out_msg[o]     = fmaxf(inp[o]     + acc[mi][ni][2], 0.f);
                out_msg[o + 1] = fmaxf(inp[o + 1] + acc[mi][ni][3], 0.f);
            }
        }
    }
}

// ---- GEMM 3 (readout): ahid = relu([f_atoms | amsg] @ W_o + b_o) ----
__global__ __launch_bounds__(256)
void gemm_o_tc(const float* __restrict__ f_atoms, const float* __restrict__ amsg,
               const float* __restrict__ B, const float* __restrict__ bias,
               float* __restrict__ out, int M, int AF, int Hh, int N)
{
    __shared__ uint32_t As[BM][SK];
    __shared__ uint32_t Bs[BN][SK];
    const int tid = threadIdx.x;
    const int lane = tid & 31, wid = tid >> 5;
    const int wm = wid >> 2, wn = wid & 3;
    const int g = lane >> 2, tg = lane & 3;
    const int rowBase = blockIdx.y * BM, colBase = blockIdx.x * BN;
    const int K = AF + Hh;

    float acc[4][4][4] = {};

    const int arow = tid >> 1;
    const int acb = (tid & 1) * 8;
    const int gr0 = rowBase + arow;
    const bool rok = gr0 < M;
    const int grc = rok ? gr0 : (M - 1);
    const float* pf = f_atoms + (size_t)grc * AF;
    const float* pm = amsg + (size_t)grc * Hh;

    for (int kk = 0; kk < K; kk += BK) {
        #pragma unroll
        for (int j = 0; j < 8; ++j) {
            int gk = kk + acb + j;
            float v = 0.f;
            if (rok && gk < K)
                v = (gk < AF) ? pf[gk] : pm[gk - AF];
            As[arow][acb + j] = f2tf(v);
        }
        stage_B(Bs, B, kk, colBase, K, N, tid);
        __syncthreads();
        compute_tile(As, Bs, acc, wm, wn, g, tg);
        __syncthreads();
    }

    #pragma unroll
    for (int mi = 0; mi < 4; ++mi) {
        int r0 = rowBase + wm * 64 + mi * 16 + g;
        #pragma unroll
        for (int ni = 0; ni < 4; ++ni) {
            int c0 = colBase + wn * 32 + ni * 8 + 2 * tg;
            if (c0 >= N) continue;
            float b0 = bias[c0], b1 = bias[c0 + 1];
            if (r0 < M) {
                size_t o = (size_t)r0 * N + c0;
                out[o]     = fmaxf(acc[mi][ni][0] + b0, 0.f);
                out[o + 1] = fmaxf(acc[mi][ni][1] + b1, 0.f);
            }
            if (r0 + 8 < M) {
                size_t o = (size_t)(r0 + 8) * N + c0;
                out[o]     = fmaxf(acc[mi][ni][2] + b0, 0.f);
                out[o + 1] = fmaxf(acc[mi][ni][3] + b1, 0.f);
            }
        }
    }
}

// ---- Gather: amsg[a] = sum_nb msg[a2b[a][nb]]  (float4 over H) ----
__global__ void gather_atoms_kernel(const float* __restrict__ msg, const int* __restrict__ a2b,
                                    float* __restrict__ amsg, int n_atoms, int max_nb)
{
    int idx = blockIdx.x * blockDim.x + threadIdx.x;
    int total = n_atoms * H4_DIM;
    if (idx >= total) return;
    int atom = idx / H4_DIM;
    int h4   = idx - atom * H4_DIM;
    float4 s = make_float4(0.f, 0.f, 0.f, 0.f);
    for (int nb = 0; nb < max_nb; ++nb) {
        int b = __ldg(&a2b[(size_t)atom * max_nb + nb]);
        float4 v = *((const float4*)(msg + (size_t)b * H_DIM) + h4);
        s.x += v.x; s.y += v.y; s.z += v.z; s.w += v.w;
    }
    ((float4*)amsg)[idx] = s;
}

// ---- Segment mean over sorted mol ids ----
__global__ void segmean_kernel(const float* __restrict__ ahid, const int* __restrict__ atom_mol,
                               float* __restrict__ out, int n_atoms, int Hh)
{
    const int m = blockIdx.x;
    __shared__ int s_bounds[2];
    if (threadIdx.x == 0) {
        int lo = 0, hi = n_atoms;
        while (lo < hi) { int mid = (lo + hi) >> 1; if (atom_mol[mid] < m) lo = mid + 1; else hi = mid; }
        s_bounds[0] = lo;
        hi = n_atoms;
        while (lo < hi) { int mid = (lo + hi) >> 1; if (atom_mol[mid] < m + 1) lo = mid + 1; else hi = mid; }
        s_bounds[1] = lo;
    }
    __syncthreads();
    const int start = s_bounds[0], end = s_bounds[1];
    const float inv = (end > start) ? 1.f / (float)(end - start) : 0.f;
    for (int h = threadIdx.x; h < Hh; h += blockDim.x) {
        float s = 0.f;
        for (int a = start; a < end; ++a) s += ahid[(size_t)a * Hh + h];
        out[(size_t)m * Hh + h] = s * inv;
    }
}

// ---------------- Launch ----------------
extern "C" void kernel_launch(void* const* d_in, const int* in_sizes, int n_in,
                              void* d_out, int out_size)
{
    const float* f_atoms = (const float*)d_in[0];
    const float* f_bonds = (const float*)d_in[1];
    const float* W_i     = (const float*)d_in[2];
    const float* W_h     = (const float*)d_in[3];
    const float* W_o     = (const float*)d_in[4];
    const float* b_o     = (const float*)d_in[5];
    const int*   a2b     = (const int*)d_in[6];
    const int*   b2a     = (const int*)d_in[7];
    const int*   b2revb  = (const int*)d_in[8];
    const int*   atom_mol= (const int*)d_in[9];

    const int H       = in_sizes[5];             // 300
    const int n_bonds = in_sizes[7];             // 200000
    const int n_atoms = in_sizes[9];             // 100000
    const int BF      = in_sizes[1] / n_bonds;   // 147
    const int AF      = in_sizes[0] / n_atoms;   // 133
    const int max_nb  = in_sizes[6] / n_atoms;   // 6
    const int n_mols  = out_size / H;            // 4000

    float* inp  = nullptr; cudaGetSymbolAddress((void**)&inp,  g_inp);
    float* msgA = nullptr; cudaGetSymbolAddress((void**)&msgA, g_msgA);
    float* msgB = nullptr; cudaGetSymbolAddress((void**)&msgB, g_msgB);
    float* amsg = nullptr; cudaGetSymbolAddress((void**)&amsg, g_amsg);
    float* ahid = nullptr; cudaGetSymbolAddress((void**)&ahid, g_ahid);

    dim3 blk(256);
    dim3 grid_b((H + BN - 1) / BN, (n_bonds + BM - 1) / BM);   // (3, 1563)
    dim3 grid_a((H + BN - 1) / BN, (n_atoms + BM - 1) / BM);   // (3, 782)

    const int thr = 256;
    int gatherBlocks = (n_atoms * H4_DIM + thr - 1) / thr;

    // 1) inp = f_bonds @ W_i ; msgA = relu(inp)
    gemm_in_tc<<<grid_b, blk>>>(f_bonds, W_i, inp, msgA, n_bonds, BF, H);

    // 2) depth 1: msgB = relu(inp + (gather/diff msgA) @ W_h)
    gather_atoms_kernel<<<gatherBlocks, thr>>>(msgA, a2b, amsg, n_atoms, max_nb);
    gemm_h_tc<<<grid_b, blk>>>(amsg, msgA, b2a, b2revb, W_h, inp, msgB, n_bonds, H, H);

    // 3) depth 2: msgA = relu(inp + (gather/diff msgB) @ W_h)
    gather_atoms_kernel<<<gatherBlocks, thr>>>(msgB, a2b, amsg, n_atoms, max_nb);
    gemm_h_tc<<<grid_b, blk>>>(amsg, msgB, b2a, b2revb, W_h, inp, msgA, n_bonds, H, H);

    // 4) final atom aggregation
    gather_atoms_kernel<<<gatherBlocks, thr>>>(msgA, a2b, amsg, n_atoms, max_nb);

    // 5) readout
    gemm_o_tc<<<grid_a, blk>>>(f_atoms, amsg, W_o, b_o, ahid, n_atoms, AF, H, H);

    // 6) per-molecule mean
    segmean_kernel<<<n_mols, 256>>>(ahid, atom_mol, (float*)d_out, n_atoms, H);
}

// round 4
// speedup vs baseline: 1.6930x; 1.4574x over previous
#include <cuda_runtime.h>
#include <cstdint>

// ---------------- Problem-size constants (fixed instance) ----------------
#define N_ATOMS_MAX  100000
#define N_BONDS_MAX  200000
#define H_DIM        300
#define H4_DIM       75

// ---------------- Device scratch (static, allocation-free) ----------------
__device__ float g_inp [(size_t)N_BONDS_MAX * H_DIM];
__device__ float g_msgA[(size_t)N_BONDS_MAX * H_DIM];
__device__ float g_msgB[(size_t)N_BONDS_MAX * H_DIM];
__device__ float g_amsg[(size_t)N_ATOMS_MAX * H_DIM];
__device__ float g_ahid[(size_t)N_ATOMS_MAX * H_DIM];

// Arch-feature gate: tcgen05 exists only in the arch-specific (sm_103a/sm_100a)
// device passes. Non-'a' passes (compute_103 PTX) get the mma.sync fallback.
#if defined(__CUDA_ARCH_FEAT_SM103_ALL) || defined(__CUDA_ARCH_FEAT_SM100_ALL) || defined(__CUDA_ARCH_SPECIFIC__)
#define USE_TC5 1
#else
#define USE_TC5 0
#endif

#define BM 128
#define BN 128

// ---------------- common helpers ----------------
__device__ __forceinline__ uint32_t f2tf(float f) {
    uint32_t u;
    asm("cvt.rna.tf32.f32 %0, %1;" : "=r"(u) : "f"(f));
    return u;
}
__device__ __forceinline__ uint32_t smem_u32(const void* p) {
    uint32_t a;
    asm("{ .reg .u64 t; cvta.to.shared.u64 t, %1; cvt.u32.u64 %0, t; }" : "=r"(a) : "l"(p));
    return a;
}
__device__ __forceinline__ uint32_t sw128(uint32_t off) { return off ^ ((off >> 3) & 0x70); }

// ---------------- tcgen05 helpers (only referenced under USE_TC5) ----------------
#if USE_TC5
#define KC 32          // K-chunk: 32 tf32 = 128B rows (SW128)
#define TMEM_COLS 128
// idesc: bit4 dtype=F32 | atype TF32=2 @7 | btype TF32=2 @10 | (N/8)@17 | (M/16)@24
#define MMA_IDESC ((1u<<4) | (2u<<7) | (2u<<10) | ((BN/8u)<<17) | ((BM/16u)<<24))

__device__ __forceinline__ bool elect_one() {
    uint32_t p;
    asm volatile("{ .reg .pred P; elect.sync _|P, 0xFFFFFFFF; selp.b32 %0, 1, 0, P; }" : "=r"(p));
    return p != 0;
}
__device__ __forceinline__ uint64_t make_desc_sw128(uint32_t addr) {
    return (uint64_t)((addr >> 4) & 0x3FFF)
         | ((uint64_t)1  << 16) | ((uint64_t)64 << 32)
         | ((uint64_t)1  << 46) | ((uint64_t)2  << 61);
}
__device__ __forceinline__ void tmem_alloc(uint32_t smem_dst, uint32_t ncols) {
    asm volatile("tcgen05.alloc.cta_group::1.sync.aligned.shared::cta.b32 [%0], %1;"
                 :: "r"(smem_dst), "r"(ncols) : "memory");
}
__device__ __forceinline__ void tmem_relinquish() {
    asm volatile("tcgen05.relinquish_alloc_permit.cta_group::1.sync.aligned;");
}
__device__ __forceinline__ void tmem_dealloc(uint32_t tmem, uint32_t ncols) {
    asm volatile("tcgen05.dealloc.cta_group::1.sync.aligned.b32 %0, %1;" :: "r"(tmem), "r"(ncols));
}
__device__ __forceinline__ void mbar_init(uint32_t mb, uint32_t cnt) {
    asm volatile("mbarrier.init.shared.b64 [%0], %1;" :: "r"(mb), "r"(cnt) : "memory");
}
__device__ __forceinline__ void mbar_wait(uint32_t mb, uint32_t parity) {
    asm volatile(
        "{\n\t.reg .pred P;\n\t"
        "WL_%=:\n\t"
        "mbarrier.try_wait.parity.acquire.cta.shared::cta.b64 P, [%0], %1, 0x989680;\n\t"
        "@!P bra WL_%=;\n\t}"
        :: "r"(mb), "r"(parity) : "memory");
}
__device__ __forceinline__ void mma_tf32_ss(uint32_t d, uint64_t a, uint64_t b,
                                            uint32_t idesc, uint32_t en) {
    asm volatile(
        "{\n\t.reg .pred p;\n\tsetp.ne.u32 p, %4, 0;\n\t"
        "tcgen05.mma.cta_group::1.kind::tf32 [%0], %1, %2, %3, {%5, %5, %5, %5}, p;\n\t}"
        :: "r"(d), "l"(a), "l"(b), "r"(idesc), "r"(en), "r"(0u) : "memory");
}
__device__ __forceinline__ void mma_commit(uint32_t mb) {
    asm volatile("tcgen05.commit.cta_group::1.mbarrier::arrive::one.shared::cluster.b64 [%0];"
                 :: "r"(mb) : "memory");
}
__device__ __forceinline__ void ldtm_x32(uint32_t* r, uint32_t tmem) {
    asm volatile(
        "tcgen05.ld.sync.aligned.32x32b.x32.b32 "
        "{%0,%1,%2,%3,%4,%5,%6,%7,%8,%9,%10,%11,%12,%13,%14,%15,"
        "%16,%17,%18,%19,%20,%21,%22,%23,%24,%25,%26,%27,%28,%29,%30,%31}, [%32];"
        : "=r"(r[0]), "=r"(r[1]), "=r"(r[2]), "=r"(r[3]), "=r"(r[4]), "=r"(r[5]), "=r"(r[6]), "=r"(r[7]),
          "=r"(r[8]), "=r"(r[9]), "=r"(r[10]), "=r"(r[11]), "=r"(r[12]), "=r"(r[13]), "=r"(r[14]), "=r"(r[15]),
          "=r"(r[16]), "=r"(r[17]), "=r"(r[18]), "=r"(r[19]), "=r"(r[20]), "=r"(r[21]), "=r"(r[22]), "=r"(r[23]),
          "=r"(r[24]), "=r"(r[25]), "=r"(r[26]), "=r"(r[27]), "=r"(r[28]), "=r"(r[29]), "=r"(r[30]), "=r"(r[31])
        : "r"(tmem));
}
__device__ __forceinline__ void tmem_wait_ld() {
    asm volatile("tcgen05.wait::ld.sync.aligned;" ::: "memory");
}
__device__ __forceinline__ void tc5_fence_after() {
    asm volatile("tcgen05.fence::after_thread_sync;" ::: "memory");
}
__device__ __forceinline__ void tc5_fence_before() {
    asm volatile("tcgen05.fence::before_thread_sync;" ::: "memory");
}
__device__ __forceinline__ void fence_proxy_async_cta() {
    asm volatile("fence.proxy.async.shared::cta;" ::: "memory");
}
#endif // USE_TC5

// ---------------- mma.sync fallback helpers ----------------
#define BKF 16
#define SKF 20
__device__ __forceinline__ void mma8(float* c, const uint32_t* a, const uint32_t* b) {
    asm volatile(
        "mma.sync.aligned.m16n8k8.row.col.f32.tf32.tf32.f32 "
        "{%0,%1,%2,%3}, {%4,%5,%6,%7}, {%8,%9}, {%0,%1,%2,%3};\n"
        : "+f"(c[0]), "+f"(c[1]), "+f"(c[2]), "+f"(c[3])
        : "r"(a[0]), "r"(a[1]), "r"(a[2]), "r"(a[3]), "r"(b[0]), "r"(b[1]));
}

// ---------------- Unified GEMM ----------------
// MODE 0: out0 = A0 @ W ; out1 = relu(out0)
// MODE 1: out0 = relu(aux + (A0[b2a[r]] - A1[b2revb[r]]) @ W)
// MODE 2: out0 = relu([A0 | A1] @ W + aux(bias))
template<int MODE>
__global__ __launch_bounds__(256)
void gemm_tc5(const float* __restrict__ A0, const float* __restrict__ A1,
              const int* __restrict__ b2a, const int* __restrict__ b2revb,
              const float* __restrict__ W, const float* __restrict__ aux,
              float* __restrict__ out0, float* __restrict__ out1,
              int M, int K, int N, int AF)
{
    const int tid  = threadIdx.x;
    const int lane = tid & 31;
    const int wid  = tid >> 5;
    const int rowBase = blockIdx.y * BM;
    const int colBase = blockIdx.x * BN;

    __shared__ const float* s_p0[BM];
    __shared__ const float* s_p1[BM];
    if (tid < BM) {
        int gr = rowBase + tid;
        if (gr >= M) gr = M - 1;
        if (MODE == 0) {
            s_p0[tid] = A0 + (size_t)gr * K;
        } else if (MODE == 1) {
            s_p0[tid] = A0 + (size_t)b2a[gr] * K;
            s_p1[tid] = A1 + (size_t)b2revb[gr] * K;
        } else {
            s_p0[tid] = A0 + (size_t)gr * AF;
            s_p1[tid] = A1 + (size_t)gr * (K - AF);
        }
    }

#if USE_TC5
    // ================= tcgen05 tf32 path =================
    __shared__ alignas(1024) uint32_t sA[BM * KC];   // 16 KB
    __shared__ alignas(1024) uint32_t sB[BN * KC];   // 16 KB
    __shared__ uint32_t s_tmem;
    __shared__ alignas(8) uint64_t s_mbar;

    if (wid == 0) {
        tmem_alloc(smem_u32(&s_tmem), TMEM_COLS);
        tmem_relinquish();
    }
    if (tid == 0) mbar_init(smem_u32(&s_mbar), 1);
    __syncthreads();

    const uint32_t tmem = s_tmem;
    const uint32_t mb   = smem_u32(&s_mbar);
    const uint64_t adesc = make_desc_sw128(smem_u32(sA));
    const uint64_t bdesc = make_desc_sw128(smem_u32(sB));

    uint32_t ph = 0;
    const int NC = (K + KC - 1) / KC;

    for (int ci = 0; ci < NC; ++ci) {
        const int kk = ci * KC;

        // stage A: lane = k, each warp covers 16 rows
        {
            const int gk = kk + lane;
            const bool kok = gk < K;
            #pragma unroll
            for (int p = 0; p < 16; ++p) {
                const int r = (p << 3) + wid;
                float v = 0.f;
                if (kok) {
                    if (MODE == 0)      v = s_p0[r][gk];
                    else if (MODE == 1) v = s_p0[r][gk] - s_p1[r][gk];
                    else                v = (gk < AF) ? s_p0[r][gk] : s_p1[r][gk - AF];
                }
                const uint32_t off = (uint32_t)(r << 7) + (uint32_t)(lane << 2);
                sA[sw128(off) >> 2] = f2tf(v);
            }
        }
        // stage B: 2 threads per column, 16 k's each. Bs[n][k] = W[kk+k][colBase+n]
        {
            const int cloc = tid & 127;
            const int gc = colBase + cloc;
            const bool cok = gc < N;
            const int k0 = (tid >> 7) * 16;
            #pragma unroll
            for (int k = 0; k < 16; ++k) {
                const int gk = kk + k0 + k;
                float v = (cok && gk < K) ? W[(size_t)gk * N + gc] : 0.f;
                const uint32_t off = (uint32_t)(cloc << 7) + (uint32_t)((k0 + k) << 2);
                sB[sw128(off) >> 2] = f2tf(v);
            }
        }
        __syncthreads();

        if (wid == 0) {
            fence_proxy_async_cta();
            if (elect_one()) {
                #pragma unroll
                for (int ks = 0; ks < 4; ++ks) {
                    const uint32_t en = (ci > 0 || ks > 0) ? 1u : 0u;
                    mma_tf32_ss(tmem, adesc + (uint64_t)(ks * 2), bdesc + (uint64_t)(ks * 2),
                                MMA_IDESC, en);
                }
                mma_commit(mb);
            }
        }
        mbar_wait(mb, ph);
        ph ^= 1;
    }

    // epilogue: warp w -> rows (w&3)*32+lane ; cols (w>>2)*64 .. +63 (two x32 batches)
    tc5_fence_after();
    const int gr = rowBase + (wid & 3) * 32 + lane;
    const bool rok = gr < M;
    const int cb0 = (wid >> 2) * 2;

    #pragma unroll
    for (int bb = 0; bb < 2; ++bb) {
        const int b = cb0 + bb;
        uint32_t d[32];
        ldtm_x32(d, tmem + (uint32_t)(b * 32));
        tmem_wait_ld();
        if (rok) {
            const int cbase = colBase + b * 32;
            #pragma unroll
            for (int j = 0; j < 32; j += 4) {
                const int c = cbase + j;
                if (c + 3 < N) {
                    const size_t o = (size_t)gr * N + c;
                    float4 v = make_float4(__uint_as_float(d[j]), __uint_as_float(d[j+1]),
                                           __uint_as_float(d[j+2]), __uint_as_float(d[j+3]));
                    if (MODE == 0) {
                        *(float4*)(out0 + o) = v;
                        *(float4*)(out1 + o) = make_float4(fmaxf(v.x,0.f), fmaxf(v.y,0.f),
                                                           fmaxf(v.z,0.f), fmaxf(v.w,0.f));
                    } else if (MODE == 1) {
                        float4 i4 = *(const float4*)(aux + o);
                        *(float4*)(out0 + o) = make_float4(
                            fmaxf(i4.x+v.x,0.f), fmaxf(i4.y+v.y,0.f),
                            fmaxf(i4.z+v.z,0.f), fmaxf(i4.w+v.w,0.f));
                    } else {
                        *(float4*)(out0 + o) = make_float4(
                            fmaxf(v.x+aux[c],0.f),   fmaxf(v.y+aux[c+1],0.f),
                            fmaxf(v.z+aux[c+2],0.f), fmaxf(v.w+aux[c+3],0.f));
                    }
                } else {
                    #pragma unroll
                    for (int q = 0; q < 4; ++q) {
                        const int cc = c + q;
                        if (cc >= N) break;
                        const size_t o = (size_t)gr * N + cc;
                        const float v = __uint_as_float(d[j + q]);
                        if (MODE == 0)      { out0[o] = v; out1[o] = fmaxf(v, 0.f); }
                        else if (MODE == 1) { out0[o] = fmaxf(aux[o] + v, 0.f); }
                        else                { out0[o] = fmaxf(v + aux[cc], 0.f); }
                    }
                }
            }
        }
    }
    tc5_fence_before();
    __syncthreads();
    if (wid == 0) tmem_dealloc(tmem, TMEM_COLS);

#else
    // ================= mma.sync tf32 fallback (proven R2 path) =================
    __shared__ uint32_t As[BM][SKF];
    __shared__ uint32_t Bs[BN][SKF];
    __syncthreads();

    const int wm = wid >> 2, wn = wid & 3;
    const int g = lane >> 2, tg = lane & 3;

    float acc[4][4][4] = {};

    const int arow = tid >> 1;
    const int acb  = (tid & 1) * 8;
    const float* pa = s_p0[arow];
    const float* pb = (MODE == 0) ? nullptr : s_p1[arow];

    for (int kk = 0; kk < K; kk += BKF) {
        #pragma unroll
        for (int j = 0; j < 8; ++j) {
            int gk = kk + acb + j;
            float v = 0.f;
            if (gk < K) {
                if (MODE == 0)      v = pa[gk];
                else if (MODE == 1) v = pa[gk] - pb[gk];
                else                v = (gk < AF) ? pa[gk] : pb[gk - AF];
            }
            As[arow][acb + j] = f2tf(v);
        }
        {
            int bk = tid >> 4;
            int nb = (tid & 15) * 8;
            int gk = kk + bk;
            bool kok = gk < K;
            const float* src = W + (size_t)(kok ? gk : 0) * N;
            #pragma unroll
            for (int j = 0; j < 8; ++j) {
                int gc = colBase + nb + j;
                float v = (kok && gc < N) ? src[gc] : 0.f;
                Bs[nb + j][bk] = f2tf(v);
            }
        }
        __syncthreads();
        #pragma unroll
        for (int ks = 0; ks < BKF; ks += 8) {
            uint32_t af[4][4], bf[4][2];
            #pragma unroll
            for (int mi = 0; mi < 4; ++mi) {
                int r = wm * 64 + mi * 16 + g;
                af[mi][0] = As[r][ks + tg];
                af[mi][1] = As[r + 8][ks + tg];
                af[mi][2] = As[r][ks + tg + 4];
                af[mi][3] = As[r + 8][ks + tg + 4];
            }
            #pragma unroll
            for (int ni = 0; ni < 4; ++ni) {
                int c = wn * 32 + ni * 8 + g;
                bf[ni][0] = Bs[c][ks + tg];
                bf[ni][1] = Bs[c][ks + tg + 4];
            }
            #pragma unroll
            for (int mi = 0; mi < 4; ++mi)
                #pragma unroll
                for (int ni = 0; ni < 4; ++ni)
                    mma8(acc[mi][ni], af[mi], bf[ni]);
        }
        __syncthreads();
    }

    #pragma unroll
    for (int mi = 0; mi < 4; ++mi) {
        int r0 = rowBase + wm * 64 + mi * 16 + g;
        #pragma unroll
        for (int ni = 0; ni < 4; ++ni) {
            int c0 = colBase + wn * 32 + ni * 8 + 2 * tg;
            if (c0 >= N) continue;
            if (r0 < M) {
                size_t o = (size_t)r0 * N + c0;
                if (MODE == 0) {
                    out0[o] = acc[mi][ni][0]; out0[o+1] = acc[mi][ni][1];
                    out1[o] = fmaxf(acc[mi][ni][0],0.f); out1[o+1] = fmaxf(acc[mi][ni][1],0.f);
                } else if (MODE == 1) {
                    out0[o]   = fmaxf(aux[o]   + acc[mi][ni][0], 0.f);
                    out0[o+1] = fmaxf(aux[o+1] + acc[mi][ni][1], 0.f);
                } else {
                    out0[o]   = fmaxf(acc[mi][ni][0] + aux[c0],   0.f);
                    out0[o+1] = fmaxf(acc[mi][ni][1] + aux[c0+1], 0.f);
                }
            }
            if (r0 + 8 < M) {
                size_t o = (size_t)(r0 + 8) * N + c0;
                if (MODE == 0) {
                    out0[o] = acc[mi][ni][2]; out0[o+1] = acc[mi][ni][3];
                    out1[o] = fmaxf(acc[mi][ni][2],0.f); out1[o+1] = fmaxf(acc[mi][ni][3],0.f);
                } else if (MODE == 1) {
                    out0[o]   = fmaxf(aux[o]   + acc[mi][ni][2], 0.f);
                    out0[o+1] = fmaxf(aux[o+1] + acc[mi][ni][3], 0.f);
                } else {
                    out0[o]   = fmaxf(acc[mi][ni][2] + aux[c0],   0.f);
                    out0[o+1] = fmaxf(acc[mi][ni][3] + aux[c0+1], 0.f);
                }
            }
        }
    }
#endif
}

// ---- Gather: amsg[a] = sum_nb msg[a2b[a][nb]]  (float4 over H) ----
__global__ void gather_atoms_kernel(const float* __restrict__ msg, const int* __restrict__ a2b,
                                    float* __restrict__ amsg, int n_atoms, int max_nb)
{
    int idx = blockIdx.x * blockDim.x + threadIdx.x;
    int total = n_atoms * H4_DIM;
    if (idx >= total) return;
    int atom = idx / H4_DIM;
    int h4   = idx - atom * H4_DIM;
    float4 s = make_float4(0.f, 0.f, 0.f, 0.f);
    for (int nb = 0; nb < max_nb; ++nb) {
        int b = __ldg(&a2b[(size_t)atom * max_nb + nb]);
        float4 v = *((const float4*)(msg + (size_t)b * H_DIM) + h4);
        s.x += v.x; s.y += v.y; s.z += v.z; s.w += v.w;
    }
    ((float4*)amsg)[idx] = s;
}

// ---- Segment mean over sorted mol ids ----
__global__ void segmean_kernel(const float* __restrict__ ahid, const int* __restrict__ atom_mol,
                               float* __restrict__ out, int n_atoms, int Hh)
{
    const int m = blockIdx.x;
    __shared__ int s_bounds[2];
    if (threadIdx.x == 0) {
        int lo = 0, hi = n_atoms;
        while (lo < hi) { int mid = (lo + hi) >> 1; if (atom_mol[mid] < m) lo = mid + 1; else hi = mid; }
        s_bounds[0] = lo;
        hi = n_atoms;
        while (lo < hi) { int mid = (lo + hi) >> 1; if (atom_mol[mid] < m + 1) lo = mid + 1; else hi = mid; }
        s_bounds[1] = lo;
    }
    __syncthreads();
    const int start = s_bounds[0], end = s_bounds[1];
    const float inv = (end > start) ? 1.f / (float)(end - start) : 0.f;
    for (int h = threadIdx.x; h < Hh; h += blockDim.x) {
        float s = 0.f;
        for (int a = start; a < end; ++a) s += ahid[(size_t)a * Hh + h];
        out[(size_t)m * Hh + h] = s * inv;
    }
}

// ---------------- Launch ----------------
extern "C" void kernel_launch(void* const* d_in, const int* in_sizes, int n_in,
                              void* d_out, int out_size)
{
    const float* f_atoms = (const float*)d_in[0];
    const float* f_bonds = (const float*)d_in[1];
    const float* W_i     = (const float*)d_in[2];
    const float* W_h     = (const float*)d_in[3];
    const float* W_o     = (const float*)d_in[4];
    const float* b_o     = (const float*)d_in[5];
    const int*   a2b     = (const int*)d_in[6];
    const int*   b2a     = (const int*)d_in[7];
    const int*   b2revb  = (const int*)d_in[8];
    const int*   atom_mol= (const int*)d_in[9];

    const int H       = in_sizes[5];             // 300
    const int n_bonds = in_sizes[7];             // 200000
    const int n_atoms = in_sizes[9];             // 100000
    const int BF      = in_sizes[1] / n_bonds;   // 147
    const int AF      = in_sizes[0] / n_atoms;   // 133
    const int max_nb  = in_sizes[6] / n_atoms;   // 6
    const int n_mols  = out_size / H;            // 4000

    float* inp  = nullptr; cudaGetSymbolAddress((void**)&inp,  g_inp);
    float* msgA = nullptr; cudaGetSymbolAddress((void**)&msgA, g_msgA);
    float* msgB = nullptr; cudaGetSymbolAddress((void**)&msgB, g_msgB);
    float* amsg = nullptr; cudaGetSymbolAddress((void**)&amsg, g_amsg);
    float* ahid = nullptr; cudaGetSymbolAddress((void**)&ahid, g_ahid);

    dim3 blk(256);
    dim3 grid_b((H + BN - 1) / BN, (n_bonds + BM - 1) / BM);
    dim3 grid_a((H + BN - 1) / BN, (n_atoms + BM - 1) / BM);

    const int thr = 256;
    int gatherBlocks = (n_atoms * H4_DIM + thr - 1) / thr;

    // 1) inp = f_bonds @ W_i ; msgA = relu(inp)
    gemm_tc5<0><<<grid_b, blk>>>(f_bonds, nullptr, nullptr, nullptr, W_i, nullptr,
                                 inp, msgA, n_bonds, BF, H, 0);

    // 2) depth 1
    gather_atoms_kernel<<<gatherBlocks, thr>>>(msgA, a2b, amsg, n_atoms, max_nb);
    gemm_tc5<1><<<grid_b, blk>>>(amsg, msgA, b2a, b2revb, W_h, inp,
                                 msgB, nullptr, n_bonds, H, H, 0);

    // 3) depth 2
    gather_atoms_kernel<<<gatherBlocks, thr>>>(msgB, a2b, amsg, n_atoms, max_nb);
    gemm_tc5<1><<<grid_b, blk>>>(amsg, msgB, b2a, b2revb, W_h, inp,
                                 msgA, nullptr, n_bonds, H, H, 0);

    // 4) final atom aggregation
    gather_atoms_kernel<<<gatherBlocks, thr>>>(msgA, a2b, amsg, n_atoms, max_nb);

    // 5) readout
    gemm_tc5<2><<<grid_a, blk>>>(f_atoms, amsg, nullptr, nullptr, W_o, b_o,
                                 ahid, nullptr, n_atoms, AF + H, H, AF);

    // 6) per-molecule mean
    segmean_kernel<<<n_mols, 256>>>(ahid, atom_mol, (float*)d_out, n_atoms, H);
}